// round 3
// baseline (speedup 1.0000x reference)
#include <cuda_runtime.h>
#include <mma.h>
using namespace nvcuda;

// ---------------- scratch (allocation-free: __device__ globals) ----------------
#define T_TOK 8192
__device__ float g_qa [T_TOK*1536];   // after wq_a (+rmsnorm in-place)
__device__ float g_q  [T_TOK*3072];   // after wq_b
__device__ float g_kva[T_TOK*576];    // after wkv_a
__device__ float g_kvn[T_TOK*512];    // normalized kv latent
__device__ float g_kpe[T_TOK*64];     // roped k_pe
__device__ float g_kv [T_TOK*4096];   // after wkv_b
__device__ float g_ao [T_TOK*2048];   // attention output

// ---------------- TF32 GEMM: C[M,N] = A[M,K] @ W[N,K]^T + bias[N] ----------------
// BM=64, BN=64, BK=32; 128 threads (4 warps), warp computes 32x32 via 2x2 wmma m16n16k8.
__global__ __launch_bounds__(128) void gemm_tf32(
    const float* __restrict__ A, const float* __restrict__ W,
    const float* __restrict__ bias, float* __restrict__ C,
    int M, int N, int K)
{
    __shared__ float As[64][40];   // ldm 40 (mult of 8 elems, rows 16B aligned)
    __shared__ float Ws[64][40];
    __shared__ float Cs[64][72];

    const int bm = blockIdx.y * 64;
    const int bn = blockIdx.x * 64;
    const int tid = threadIdx.x;
    const int warp = tid >> 5;
    const int wm = (warp >> 1) * 32;
    const int wn = (warp & 1) * 32;

    wmma::fragment<wmma::accumulator, 16, 16, 8, float> acc[2][2];
#pragma unroll
    for (int i = 0; i < 2; i++)
#pragma unroll
        for (int j = 0; j < 2; j++) wmma::fill_fragment(acc[i][j], 0.0f);

    for (int k0 = 0; k0 < K; k0 += 32) {
        // stage A 64x32 and W 64x32 tiles (512 float4 each, 4 per thread)
#pragma unroll
        for (int i = tid; i < 512; i += 128) {
            int r = i >> 3, c = i & 7;
            *(float4*)&As[r][c * 4] = *(const float4*)(A + (size_t)(bm + r) * K + k0 + c * 4);
            *(float4*)&Ws[r][c * 4] = *(const float4*)(W + (size_t)(bn + r) * K + k0 + c * 4);
        }
        __syncthreads();
#pragma unroll
        for (int kk = 0; kk < 32; kk += 8) {
            wmma::fragment<wmma::matrix_a, 16, 16, 8, wmma::precision::tf32, wmma::row_major> af[2];
            wmma::fragment<wmma::matrix_b, 16, 16, 8, wmma::precision::tf32, wmma::col_major> bf[2];
#pragma unroll
            for (int i = 0; i < 2; i++) {
                wmma::load_matrix_sync(af[i], &As[wm + i * 16][kk], 40);
#pragma unroll
                for (int e = 0; e < af[i].num_elements; e++)
                    af[i].x[e] = wmma::__float_to_tf32(af[i].x[e]);
                wmma::load_matrix_sync(bf[i], &Ws[wn + i * 16][kk], 40);
#pragma unroll
                for (int e = 0; e < bf[i].num_elements; e++)
                    bf[i].x[e] = wmma::__float_to_tf32(bf[i].x[e]);
            }
#pragma unroll
            for (int i = 0; i < 2; i++)
#pragma unroll
                for (int j = 0; j < 2; j++)
                    wmma::mma_sync(acc[i][j], af[i], bf[j], acc[i][j]);
        }
        __syncthreads();
    }

#pragma unroll
    for (int i = 0; i < 2; i++)
#pragma unroll
        for (int j = 0; j < 2; j++)
            wmma::store_matrix_sync(&Cs[wm + i * 16][wn + j * 16], acc[i][j], 72, wmma::mem_row_major);
    __syncthreads();

#pragma unroll
    for (int i = tid; i < 1024; i += 128) {
        int r = i >> 4, c = i & 15;
        float4 v  = *(float4*)&Cs[r][c * 4];
        float4 bq = *(const float4*)(bias + bn + c * 4);
        v.x += bq.x; v.y += bq.y; v.z += bq.z; v.w += bq.w;
        *(float4*)(C + (size_t)(bm + r) * N + bn + c * 4) = v;
    }
}

// ---------------- RMSNorm (in-place, one block per row) ----------------
__global__ __launch_bounds__(256) void rmsnorm_inplace(
    float* __restrict__ data, const float* __restrict__ w, int W)
{
    const int t = blockIdx.x, tid = threadIdx.x;
    float* p = data + (size_t)t * W;
    float ss = 0.f;
    for (int i = tid; i < W; i += 256) { float v = p[i]; ss += v * v; }
    __shared__ float red[256];
    red[tid] = ss; __syncthreads();
    for (int w2 = 128; w2 > 0; w2 >>= 1) {
        if (tid < w2) red[tid] += red[tid + w2];
        __syncthreads();
    }
    const float inv = rsqrtf(red[0] / (float)W + 1.1920929e-7f);
    for (int i = tid; i < W; i += 256) p[i] = p[i] * inv * w[i];
}

// ---------------- kv_a post-process: rmsnorm(512) + rope(last 64) ----------------
__global__ __launch_bounds__(128) void kv_prep(
    const float* __restrict__ kva, const float* __restrict__ knw,
    const float* __restrict__ cosb, const float* __restrict__ sinb,
    float* __restrict__ kvn, float* __restrict__ kpe, int S)
{
    const int t = blockIdx.x, tid = threadIdx.x;
    const int s = t % S;
    const float* src = kva + (size_t)t * 576;
    float ss = 0.f;
    for (int i = tid; i < 512; i += 128) { float v = src[i]; ss += v * v; }
    __shared__ float red[128];
    red[tid] = ss; __syncthreads();
    for (int w2 = 64; w2 > 0; w2 >>= 1) {
        if (tid < w2) red[tid] += red[tid + w2];
        __syncthreads();
    }
    const float inv = rsqrtf(red[0] / 512.0f + 1.1920929e-7f);
    for (int i = tid; i < 512; i += 128) kvn[(size_t)t * 512 + i] = src[i] * inv * knw[i];
    if (tid < 32) {
        const int j = tid;
        const float c = cosb[s * 32 + j], sn = sinb[s * 32 + j];
        const float x0 = src[512 + 2 * j], x1 = src[512 + 2 * j + 1];
        kpe[(size_t)t * 64 + 2 * j]     = x0 * c  - x1 * sn;
        kpe[(size_t)t * 64 + 2 * j + 1] = x0 * sn + x1 * c;
    }
}

// ---------------- per-token attention: rope(q_pe) + 16x16 scores + softmax + attn@V ----------------
#define ATT_SCALE 0.07216878364870322f  // (128+64)^-0.5
__global__ __launch_bounds__(128) void attn_kernel(
    const float* __restrict__ q, const float* __restrict__ kv,
    const float* __restrict__ kpe, const float* __restrict__ cosb,
    const float* __restrict__ sinb, float* __restrict__ out, int S)
{
    const int t = blockIdx.x, tid = threadIdx.x;
    const int s = t % S;
    __shared__ float qs[3072];
    __shared__ float kvs[16 * 260];   // stride 260: rows 16B aligned, conflict-free-ish
    __shared__ float kp[64];
    __shared__ float sc[16][17];

    const float* qg = q + (size_t)t * 3072;
    for (int i = tid; i < 768; i += 128) ((float4*)qs)[i] = ((const float4*)qg)[i];
    const float* kvg = kv + (size_t)t * 4096;
    for (int i = tid; i < 1024; i += 128) {
        int g = i >> 6, c = i & 63;
        *(float4*)&kvs[g * 260 + c * 4] = *(const float4*)(kvg + g * 256 + c * 4);
    }
    if (tid < 16) ((float4*)kp)[tid] = ((const float4*)(kpe + (size_t)t * 64))[tid];
    __syncthreads();

    // rope q_pe in shared: 16 heads x 32 pairs
    for (int p = tid; p < 512; p += 128) {
        const int h = p >> 5, j = p & 31;
        const float c = cosb[s * 32 + j], sn = sinb[s * 32 + j];
        const int i0 = h * 192 + 128 + 2 * j;
        const float x0 = qs[i0], x1 = qs[i0 + 1];
        qs[i0]     = x0 * c  - x1 * sn;
        qs[i0 + 1] = x0 * sn + x1 * c;
    }
    __syncthreads();

    // scores: thread -> (h = tid>>3, g0 = tid&7, g1 = g0+8)
    {
        const int h = tid >> 3, g0 = tid & 7, g1 = g0 + 8;
        const float* qh = &qs[h * 192];
        const float* k0 = &kvs[g0 * 260];
        const float* k1 = &kvs[g1 * 260];
        float a0 = 0.f, a1 = 0.f;
#pragma unroll 8
        for (int d = 0; d < 128; d++) { const float qd = qh[d]; a0 += qd * k0[d]; a1 += qd * k1[d]; }
        float pe = 0.f;
        const float* qp = &qs[h * 192 + 128];
#pragma unroll 8
        for (int d = 0; d < 64; d++) pe += qp[d] * kp[d];
        sc[h][g0] = (a0 + pe) * ATT_SCALE;
        sc[h][g1] = (a1 + pe) * ATT_SCALE;
    }
    __syncthreads();

    if (tid < 16) {
        float m = -1e30f;
#pragma unroll
        for (int g = 0; g < 16; g++) m = fmaxf(m, sc[tid][g]);
        float sum = 0.f;
#pragma unroll
        for (int g = 0; g < 16; g++) { const float e = expf(sc[tid][g] - m); sc[tid][g] = e; sum += e; }
        const float r = 1.f / sum;
#pragma unroll
        for (int g = 0; g < 16; g++) sc[tid][g] *= r;
    }
    __syncthreads();

    // out[h][d] = sum_g attn[h][g] * v[g][d];  iteration k: all threads on head k, d = tid
    for (int o = tid; o < 2048; o += 128) {
        const int h = o >> 7, d = o & 127;
        float acc = 0.f;
#pragma unroll
        for (int g = 0; g < 16; g++) acc += sc[h][g] * kvs[g * 260 + 128 + d];
        out[(size_t)t * 2048 + o] = acc;
    }
}

// ---------------- host launcher ----------------
extern "C" void kernel_launch(void* const* d_in, const int* in_sizes, int n_in,
                              void* d_out, int out_size)
{
    const float* x     = (const float*)d_in[0];
    const float* fcos  = (const float*)d_in[1];
    const float* fsin  = (const float*)d_in[2];
    const float* wqa   = (const float*)d_in[3];
    const float* wqab  = (const float*)d_in[4];
    const float* qnw   = (const float*)d_in[5];
    const float* wqb   = (const float*)d_in[6];
    const float* wqbb  = (const float*)d_in[7];
    const float* wkva  = (const float*)d_in[8];
    const float* wkvab = (const float*)d_in[9];
    const float* kvnw  = (const float*)d_in[10];
    const float* wkvb  = (const float*)d_in[11];
    const float* wkvbb = (const float*)d_in[12];
    const float* wo    = (const float*)d_in[13];
    const float* wob   = (const float*)d_in[14];
    float* out = (float*)d_out;

    const int T = in_sizes[0] / 2048;   // B*S tokens (8192)
    const int S = in_sizes[1] / 32;     // 2048

    float *qa, *qq, *kva, *kvn, *kpe, *kv, *ao;
    cudaGetSymbolAddress((void**)&qa,  g_qa);
    cudaGetSymbolAddress((void**)&qq,  g_q);
    cudaGetSymbolAddress((void**)&kva, g_kva);
    cudaGetSymbolAddress((void**)&kvn, g_kvn);
    cudaGetSymbolAddress((void**)&kpe, g_kpe);
    cudaGetSymbolAddress((void**)&kv,  g_kv);
    cudaGetSymbolAddress((void**)&ao,  g_ao);

    const dim3 blk(128);
    // q path
    gemm_tf32<<<dim3(1536 / 64, T / 64), blk>>>(x,   wqa,  wqab,  qa,  T, 1536, 2048);
    rmsnorm_inplace<<<T, 256>>>(qa, qnw, 1536);
    gemm_tf32<<<dim3(3072 / 64, T / 64), blk>>>(qa,  wqb,  wqbb,  qq,  T, 3072, 1536);
    // kv path
    gemm_tf32<<<dim3(576 / 64,  T / 64), blk>>>(x,   wkva, wkvab, kva, T, 576,  2048);
    kv_prep<<<T, 128>>>(kva, kvnw, fcos, fsin, kvn, kpe, S);
    gemm_tf32<<<dim3(4096 / 64, T / 64), blk>>>(kvn, wkvb, wkvbb, kv,  T, 4096, 512);
    // attention + output projection
    attn_kernel<<<T, 128>>>(qq, kv, kpe, fcos, fsin, ao, S);
    gemm_tf32<<<dim3(2048 / 64, T / 64), blk>>>(ao,  wo,   wob,   out, T, 2048, 2048);
}